// round 4
// baseline (speedup 1.0000x reference)
#include <cuda_runtime.h>
#include <math.h>

#define B 64
#define C 256
#define HW 64
#define L 21

// [f][b][l][c] window-average values, fp32, bit-matching reference f4
__device__ float g_f4[2 * B * L * C];
__device__ double g_kl[L];

// ---------------------------------------------------------------------------
// Kernel A: emulate jnp.cumsum (associative_scan tree, fp32) integral image,
// 4-corner rect, /s. One block handles (f, b, 8-channel chunk).
//
// associative_scan tree (n=64, all levels even):
//   up:   A_k[i] = A_{k-1}[2i] + A_{k-1}[2i+1]          (A_0 = x)
//   down: S_6 = A_6;  S_k[0] = A_k[0];
//         S_k[2i+1] = S_{k+1}[i];  S_k[2i] = S_{k+1}[i-1] + A_k[2i]  (i>=1)
//   (in-place: S_k overwrites A_k; only same-index per-thread hazards)
// ---------------------------------------------------------------------------
__global__ __launch_bounds__(256) void pool_kernel(
    const float* __restrict__ f1, const float* __restrict__ f2,
    const float* __restrict__ pre1, const float* __restrict__ pre2)
{
    __shared__ float T[64][65];    // x -> scanH result -> P2
    __shared__ float PY[64][65];   // pyramid slabs (rows for scanH, cols for scanW)
    __shared__ int s_left[L], s_right[L], s_down[L], s_upper[L];
    __shared__ float s_s[L];

    const int CPB = 8;             // channels per block
    const int NCHUNK = C / CPB;    // 32
    int bx = blockIdx.x;
    int chunk = bx % NCHUNK;
    int fb = bx / NCHUNK;
    int b = fb % B;
    int f = fb / B;

    const float* feat = f ? f2 : f1;
    const float* pre  = f ? pre2 : pre1;

    int tid = threadIdx.x;
    if (tid < L) {
        float x = pre[(b * L + tid) * 2 + 0];
        float y = pre[(b * L + tid) * 2 + 1];
        int left  = (int)fmaxf(x - 6.0f, 0.0f);   // clamp then trunc (non-neg)
        int right = (int)fminf(x + 6.0f, 63.0f);
        int down  = (int)fmaxf(y - 6.0f, 0.0f);
        int upper = (int)fminf(y + 6.0f, 63.0f);
        s_left[tid] = left;  s_right[tid] = right;
        s_down[tid] = down;  s_upper[tid] = upper;
        // divisor uses INCLUSIVE window (faithful quirk), int -> float exact
        s_s[tid] = (float)((upper - down + 1) * (right - left + 1));
    }

    int c0 = chunk * CPB;
    for (int cc = 0; cc < CPB; ++cc) {
        int c = c0 + cc;
        const float4* src = (const float4*)(feat + ((size_t)b * C + c) * (HW * HW));
        __syncthreads();  // protect T/PY reuse + s_ visibility (1st iter)

        // ---- load 64x64 tile (1024 float4, coalesced) ----
        for (int i = tid; i < 1024; i += 256) {
            float4 v = src[i];
            int h = i >> 4, w = (i & 15) * 4;
            T[h][w + 0] = v.x; T[h][w + 1] = v.y;
            T[h][w + 2] = v.z; T[h][w + 3] = v.w;
        }
        __syncthreads();

        // ================= scan over h (axis 2) =================
        // up-sweep: slabs at PY rows {L1:0, L2:32, L3:48, L4:56, L5:60, L6:62}
        for (int e = tid; e < 2048; e += 256) {       // level 1 from T
            int i = e >> 6, w = e & 63;
            PY[i][w] = __fadd_rn(T[2 * i][w], T[2 * i + 1][w]);
        }
        __syncthreads();
#define UPH(OP, ON, N2)                                                   \
        for (int e = tid; e < (N2) * 64; e += 256) {                      \
            int i = e >> 6, w = e & 63;                                   \
            PY[(ON) + i][w] = __fadd_rn(PY[(OP) + 2 * i][w],              \
                                        PY[(OP) + 2 * i + 1][w]);         \
        }                                                                 \
        __syncthreads();
        UPH(0, 32, 16) UPH(32, 48, 8) UPH(48, 56, 4) UPH(56, 60, 2) UPH(60, 62, 1)

        // down-sweep (in place), k = 5..1 then level 0 on T
#define DNH(O, ON, NK)                                                    \
        for (int e = tid; e < (NK) * 64; e += 256) {                      \
            int j = e >> 6, w = e & 63;                                   \
            if (j) {                                                      \
                if (j & 1) PY[(O) + j][w] = PY[(ON) + (j >> 1)][w];       \
                else PY[(O) + j][w] =                                     \
                    __fadd_rn(PY[(ON) + (j >> 1) - 1][w], PY[(O) + j][w]);\
            }                                                             \
        }                                                                 \
        __syncthreads();
        DNH(60, 62, 2) DNH(56, 60, 4) DNH(48, 56, 8) DNH(32, 48, 16) DNH(0, 32, 32)
        for (int e = tid; e < 4096; e += 256) {       // level 0 on T
            int j = e >> 6, w = e & 63;
            if (j) {
                if (j & 1) T[j][w] = PY[j >> 1][w];
                else T[j][w] = __fadd_rn(PY[(j >> 1) - 1][w], T[j][w]);
            }
        }
        __syncthreads();

        // ================= scan over w (axis 3) =================
        // up-sweep: slabs at PY cols {L1:0, L2:32, L3:48, L4:56, L5:60, L6:62}
        for (int e = tid; e < 2048; e += 256) {       // level 1 from T
            int h = e >> 5, i = e & 31;
            PY[h][i] = __fadd_rn(T[h][2 * i], T[h][2 * i + 1]);
        }
        __syncthreads();
#define UPW(OP, ON, N2, SH)                                               \
        for (int e = tid; e < 64 * (N2); e += 256) {                      \
            int h = e >> (SH), i = e & ((N2) - 1);                        \
            PY[h][(ON) + i] = __fadd_rn(PY[h][(OP) + 2 * i],              \
                                        PY[h][(OP) + 2 * i + 1]);         \
        }                                                                 \
        __syncthreads();
        UPW(0, 32, 16, 4) UPW(32, 48, 8, 3) UPW(48, 56, 4, 2)
        UPW(56, 60, 2, 1) UPW(60, 62, 1, 0)

#define DNW(O, ON, NK, SH)                                                \
        for (int e = tid; e < 64 * (NK); e += 256) {                      \
            int h = e >> (SH), j = e & ((NK) - 1);                        \
            if (j) {                                                      \
                if (j & 1) PY[h][(O) + j] = PY[h][(ON) + (j >> 1)];       \
                else PY[h][(O) + j] =                                     \
                    __fadd_rn(PY[h][(ON) + (j >> 1) - 1], PY[h][(O) + j]);\
            }                                                             \
        }                                                                 \
        __syncthreads();
        DNW(60, 62, 2, 1) DNW(56, 60, 4, 2) DNW(48, 56, 8, 3)
        DNW(32, 48, 16, 4) DNW(0, 32, 32, 5)
        for (int e = tid; e < 4096; e += 256) {       // level 0 on T
            int h = e >> 6, j = e & 63;
            if (j) {
                if (j & 1) T[h][j] = PY[h][j >> 1];
                else T[h][j] = __fadd_rn(PY[h][(j >> 1) - 1], T[h][j]);
            }
        }
        __syncthreads();

        // ---- corners: padded P[i][j] = (i>0 && j>0) ? P2[i-1][j-1] : 0 ----
        if (tid < L) {
            int l = tid;
            int left = s_left[l], right = s_right[l];
            int down = s_down[l], upper = s_upper[l];
            float Pru = T[right - 1][upper - 1];               // right,upper >= 6
            float Plu = (left > 0) ? T[left - 1][upper - 1] : 0.0f;
            float Prd = (down > 0) ? T[right - 1][down - 1] : 0.0f;
            float Pld = (left > 0 && down > 0) ? T[left - 1][down - 1] : 0.0f;
            // jax eval order: ((Pru - Plu) - Prd) + Pld, fp32
            float rect = __fadd_rn(__fsub_rn(__fsub_rn(Pru, Plu), Prd), Pld);
            float f4 = rect / s_s[l];                           // IEEE fp32 div
            g_f4[(((size_t)f * B + b) * L + l) * C + c] = f4;
        }
    }
}

// ---------------------------------------------------------------------------
// Kernel B: fp32 sequential batch mean + EMA (emulating XLA), fp64 downstream.
// One block per landmark, 256 threads = channels.
// ---------------------------------------------------------------------------
__global__ __launch_bounds__(256) void kl_kernel(
    const float* __restrict__ fea1, const float* __restrict__ fea2)
{
    int l = blockIdx.x;
    int c = threadIdx.x;

    float s1 = 0.0f, s2 = 0.0f;
    for (int bb = 0; bb < B; ++bb) {                 // sequential ascending
        s1 = __fadd_rn(s1, g_f4[(((size_t)0 * B + bb) * L + l) * C + c]);
        s2 = __fadd_rn(s2, g_f4[(((size_t)1 * B + bb) * L + l) * C + c]);
    }
    float m1 = __fdiv_rn(s1, 64.0f);                 // exact (pow2)
    float m2 = __fdiv_rn(s2, 64.0f);

    const float MM = 0.999f;
    const float OM = (float)(1.0 - 0.999);
    float fc1f = __fadd_rn(__fmul_rn(MM, m1), __fmul_rn(OM, fea1[l * C + c]));
    float fc2f = __fadd_rn(__fmul_rn(MM, m2), __fmul_rn(OM, fea2[l * C + c]));

    // ---- fp64 downstream (truth; ref's fp32 downstream error ~1e-4 rel) ----
    double fc1 = (double)fc1f, fc2 = (double)fc2f;

    __shared__ double sh[8];
    int warp = c >> 5, lane = c & 31;

    // block-max fc1
    double m = fc1;
    #pragma unroll
    for (int o = 16; o > 0; o >>= 1) {
        double t = __shfl_xor_sync(0xffffffffu, m, o);
        m = fmax(m, t);
    }
    if (lane == 0) sh[warp] = m;
    __syncthreads();
    m = sh[lane & 7];
    #pragma unroll
    for (int o = 4; o > 0; o >>= 1) {
        double t = __shfl_xor_sync(0xffffffffu, m, o);
        m = fmax(m, t);
    }

    // block-sum exp(fc1 - m)
    double e = exp(fc1 - m);
    double se = e;
    #pragma unroll
    for (int o = 16; o > 0; o >>= 1) se += __shfl_xor_sync(0xffffffffu, se, o);
    __syncthreads();
    if (lane == 0) sh[warp] = se;
    __syncthreads();
    se = sh[lane & 7];
    #pragma unroll
    for (int o = 4; o > 0; o >>= 1) se += __shfl_xor_sync(0xffffffffu, se, o);

    double log_p = (fc1 - m) - log(se);

    // block-sum fc2
    double S2 = fc2;
    #pragma unroll
    for (int o = 16; o > 0; o >>= 1) S2 += __shfl_xor_sync(0xffffffffu, S2, o);
    __syncthreads();
    if (lane == 0) sh[warp] = S2;
    __syncthreads();
    S2 = sh[lane & 7];
    #pragma unroll
    for (int o = 4; o > 0; o >>= 1) S2 += __shfl_xor_sync(0xffffffffu, S2, o);

    double q = fc2 / S2;
    double term = (q > 0.0) ? q * (log(q) - log_p) : 0.0;

    // block-sum KL terms
    double kl = term;
    #pragma unroll
    for (int o = 16; o > 0; o >>= 1) kl += __shfl_xor_sync(0xffffffffu, kl, o);
    __syncthreads();
    if (lane == 0) sh[warp] = kl;
    __syncthreads();
    if (c == 0) {
        double t = 0.0;
        #pragma unroll
        for (int w = 0; w < 8; ++w) t += sh[w];
        g_kl[l] = t;
    }
}

// ---------------------------------------------------------------------------
// Kernel C: mean over 21 landmarks -> fp32 scalar.
// ---------------------------------------------------------------------------
__global__ void final_kernel(float* __restrict__ out)
{
    int t = threadIdx.x;
    double v = (t < L) ? g_kl[t] : 0.0;
    #pragma unroll
    for (int o = 16; o > 0; o >>= 1) v += __shfl_xor_sync(0xffffffffu, v, o);
    if (t == 0) out[0] = (float)(v / 21.0);
}

extern "C" void kernel_launch(void* const* d_in, const int* in_sizes, int n_in,
                              void* d_out, int out_size)
{
    const float* f1   = (const float*)d_in[0];
    const float* f2   = (const float*)d_in[1];
    const float* pre1 = (const float*)d_in[2];
    const float* pre2 = (const float*)d_in[3];
    const float* fea1 = (const float*)d_in[4];
    const float* fea2 = (const float*)d_in[5];
    float* out = (float*)d_out;

    pool_kernel<<<2 * B * (C / 8), 256>>>(f1, f2, pre1, pre2);
    kl_kernel<<<L, 256>>>(fea1, fea2);
    final_kernel<<<1, 32>>>(out);
}

// round 5
// speedup vs baseline: 3.7916x; 3.7916x over previous
#include <cuda_runtime.h>
#include <math.h>

#define B 64
#define C 256
#define HW 64
#define L 21
#define PITCH 66   // odd*2: scalar column access conflict-free, float2 row access conflict-free

// [f][l][b][c] window-average values, fp32, bit-matching reference f4
__device__ float g_f4[2 * L * B * C];
__device__ double g_kl[L];

// ---------------------------------------------------------------------------
// In-register inclusive scan over 64 elements, bit-identical to
// jax.lax.associative_scan (fp32). Up-sweep pairs adjacent blocks; down-sweep
// adds the already-final prefix to each odd-multiple position. FADD(rn) is
// commutative, so operand order matches the reference bitwise.
// ---------------------------------------------------------------------------
__device__ __forceinline__ void scan64(float (&a)[64])
{
    #pragma unroll
    for (int d = 0; d < 6; ++d) {
        #pragma unroll
        for (int i = 0; i < (64 >> (d + 1)); ++i) {
            int hi = (i << (d + 1)) + (1 << (d + 1)) - 1;
            int lo = (i << (d + 1)) + (1 << d) - 1;
            a[hi] = __fadd_rn(a[lo], a[hi]);
        }
    }
    #pragma unroll
    for (int d = 4; d >= 0; --d) {
        #pragma unroll
        for (int i = 1; i < (64 >> (d + 1)); ++i) {
            int m = (i << (d + 1)) + (1 << d) - 1;
            a[m] = __fadd_rn(a[(i << (d + 1)) - 1], a[m]);
        }
    }
}

// ---------------------------------------------------------------------------
// Kernel A: integral image via register-resident scans.
// Block = (f, b, channel pair). 128 threads: group g = tid>>6 owns channel
// cpair*2+g; t = tid&63 is the column (phase 1) / row (phase 2) index.
// ---------------------------------------------------------------------------
__global__ __launch_bounds__(128) void pool_kernel(
    const float* __restrict__ f1, const float* __restrict__ f2,
    const float* __restrict__ pre1, const float* __restrict__ pre2)
{
    __shared__ float S[2][HW][PITCH];
    __shared__ int s_left[L], s_right[L], s_down[L], s_upper[L];
    __shared__ float s_s[L];
    __shared__ unsigned long long s_mask;

    int bx = blockIdx.x;
    int cpair = bx & 127;          // C/2 = 128 channel pairs
    int fb = bx >> 7;
    int b = fb & 63;
    int f = fb >> 6;

    const float* feat = f ? f2 : f1;
    const float* pre  = f ? pre2 : pre1;

    int tid = threadIdx.x;
    int g = tid >> 6;
    int t = tid & 63;

    if (tid < L) {
        float x = pre[(b * L + tid) * 2 + 0];
        float y = pre[(b * L + tid) * 2 + 1];
        int left  = (int)fmaxf(x - 6.0f, 0.0f);   // clamp then trunc (non-neg)
        int right = (int)fminf(x + 6.0f, 63.0f);
        int down  = (int)fmaxf(y - 6.0f, 0.0f);
        int upper = (int)fminf(y + 6.0f, 63.0f);
        s_left[tid] = left;  s_right[tid] = right;
        s_down[tid] = down;  s_upper[tid] = upper;
        // divisor uses INCLUSIVE window (faithful quirk)
        s_s[tid] = (float)((upper - down + 1) * (right - left + 1));
    }

    // ---- load 64x64 tile (float2, coalesced, conflict-free STS.64) ----
    int c = cpair * 2 + g;
    const float2* src = (const float2*)(feat + ((size_t)b * C + c) * (HW * HW));
    #pragma unroll
    for (int k = 0; k < 32; ++k) {
        int i = t + k * 64;               // float2 index within tile
        float2 v = src[i];
        int h = i >> 5, w = (i & 31) * 2;
        *(float2*)&S[g][h][w] = v;
    }
    __syncthreads();

    // rows needed for corner extraction (per block; same for both channels)
    if (tid == 0) {
        unsigned long long m = 0;
        for (int l = 0; l < L; ++l) {
            m |= 1ull << (s_right[l] - 1);
            if (s_left[l] > 0) m |= 1ull << (s_left[l] - 1);
        }
        s_mask = m;
    }

    float a[64];

    // ---- phase 1: scan along h (axis 2); thread t = column w = t ----
    #pragma unroll
    for (int j = 0; j < 64; ++j) a[j] = S[g][j][t];
    scan64(a);
    #pragma unroll
    for (int j = 0; j < 64; ++j) S[g][j][t] = a[j];
    __syncthreads();

    // ---- phase 2: scan along w (axis 3); thread t = row h = t ----
    #pragma unroll
    for (int k = 0; k < 32; ++k) {
        float2 v = *(const float2*)&S[g][t][2 * k];
        a[2 * k] = v.x; a[2 * k + 1] = v.y;
    }
    scan64(a);
    if ((s_mask >> t) & 1ull) {           // write back only needed rows
        #pragma unroll
        for (int k = 0; k < 32; ++k) {
            float2 v; v.x = a[2 * k]; v.y = a[2 * k + 1];
            *(float2*)&S[g][t][2 * k] = v;
        }
    }
    __syncthreads();

    // ---- corners: padded P[i][j] = (i>0 && j>0) ? P2[i-1][j-1] : 0 ----
    if (t < L) {
        int l = t;
        int left = s_left[l], right = s_right[l];
        int down = s_down[l], upper = s_upper[l];
        float Pru = S[g][right - 1][upper - 1];           // right,upper >= 6
        float Plu = (left > 0) ? S[g][left - 1][upper - 1] : 0.0f;
        float Prd = (down > 0) ? S[g][right - 1][down - 1] : 0.0f;
        float Pld = (left > 0 && down > 0) ? S[g][left - 1][down - 1] : 0.0f;
        // jax eval order: ((Pru - Plu) - Prd) + Pld, fp32
        float rect = __fadd_rn(__fsub_rn(__fsub_rn(Pru, Plu), Prd), Pld);
        float f4 = rect / s_s[l];                          // IEEE fp32 div
        g_f4[(((size_t)f * L + l) * B + b) * C + c] = f4;
    }
}

// ---------------------------------------------------------------------------
// Kernel B: fp32 sequential batch mean + EMA (emulating XLA), fp64 downstream.
// One block per landmark, 256 threads = channels. g_f4 layout [f][l][b][c]
// gives fully contiguous reads.
// ---------------------------------------------------------------------------
__global__ __launch_bounds__(256) void kl_kernel(
    const float* __restrict__ fea1, const float* __restrict__ fea2)
{
    int l = blockIdx.x;
    int c = threadIdx.x;

    float s1 = 0.0f, s2 = 0.0f;
    for (int bb = 0; bb < B; ++bb) {                 // sequential ascending
        s1 = __fadd_rn(s1, g_f4[(((size_t)0 * L + l) * B + bb) * C + c]);
        s2 = __fadd_rn(s2, g_f4[(((size_t)1 * L + l) * B + bb) * C + c]);
    }
    float m1 = __fdiv_rn(s1, 64.0f);                 // exact (pow2)
    float m2 = __fdiv_rn(s2, 64.0f);

    const float MM = 0.999f;
    const float OM = (float)(1.0 - 0.999);
    float fc1f = __fadd_rn(__fmul_rn(MM, m1), __fmul_rn(OM, fea1[l * C + c]));
    float fc2f = __fadd_rn(__fmul_rn(MM, m2), __fmul_rn(OM, fea2[l * C + c]));

    // ---- fp64 downstream (truth; ref's fp32 downstream error ~1e-4 rel) ----
    double fc1 = (double)fc1f, fc2 = (double)fc2f;

    __shared__ double sh[8];
    int warp = c >> 5, lane = c & 31;

    // block-max fc1
    double m = fc1;
    #pragma unroll
    for (int o = 16; o > 0; o >>= 1) {
        double tt = __shfl_xor_sync(0xffffffffu, m, o);
        m = fmax(m, tt);
    }
    if (lane == 0) sh[warp] = m;
    __syncthreads();
    m = sh[lane & 7];
    #pragma unroll
    for (int o = 4; o > 0; o >>= 1) {
        double tt = __shfl_xor_sync(0xffffffffu, m, o);
        m = fmax(m, tt);
    }

    // block-sum exp(fc1 - m)
    double se = exp(fc1 - m);
    #pragma unroll
    for (int o = 16; o > 0; o >>= 1) se += __shfl_xor_sync(0xffffffffu, se, o);
    __syncthreads();
    if (lane == 0) sh[warp] = se;
    __syncthreads();
    se = sh[lane & 7];
    #pragma unroll
    for (int o = 4; o > 0; o >>= 1) se += __shfl_xor_sync(0xffffffffu, se, o);

    double log_p = (fc1 - m) - log(se);

    // block-sum fc2
    double S2 = fc2;
    #pragma unroll
    for (int o = 16; o > 0; o >>= 1) S2 += __shfl_xor_sync(0xffffffffu, S2, o);
    __syncthreads();
    if (lane == 0) sh[warp] = S2;
    __syncthreads();
    S2 = sh[lane & 7];
    #pragma unroll
    for (int o = 4; o > 0; o >>= 1) S2 += __shfl_xor_sync(0xffffffffu, S2, o);

    double q = fc2 / S2;
    double term = (q > 0.0) ? q * (log(q) - log_p) : 0.0;

    // block-sum KL terms
    double kl = term;
    #pragma unroll
    for (int o = 16; o > 0; o >>= 1) kl += __shfl_xor_sync(0xffffffffu, kl, o);
    __syncthreads();
    if (lane == 0) sh[warp] = kl;
    __syncthreads();
    if (c == 0) {
        double tt = 0.0;
        #pragma unroll
        for (int w = 0; w < 8; ++w) tt += sh[w];
        g_kl[l] = tt;
    }
}

// ---------------------------------------------------------------------------
// Kernel C: mean over 21 landmarks -> fp32 scalar.
// ---------------------------------------------------------------------------
__global__ void final_kernel(float* __restrict__ out)
{
    int t = threadIdx.x;
    double v = (t < L) ? g_kl[t] : 0.0;
    #pragma unroll
    for (int o = 16; o > 0; o >>= 1) v += __shfl_xor_sync(0xffffffffu, v, o);
    if (t == 0) out[0] = (float)(v / 21.0);
}

extern "C" void kernel_launch(void* const* d_in, const int* in_sizes, int n_in,
                              void* d_out, int out_size)
{
    const float* f1   = (const float*)d_in[0];
    const float* f2   = (const float*)d_in[1];
    const float* pre1 = (const float*)d_in[2];
    const float* pre2 = (const float*)d_in[3];
    const float* fea1 = (const float*)d_in[4];
    const float* fea2 = (const float*)d_in[5];
    float* out = (float*)d_out;

    pool_kernel<<<2 * B * (C / 2), 128>>>(f1, f2, pre1, pre2);
    kl_kernel<<<L, 256>>>(fea1, fea2);
    final_kernel<<<1, 32>>>(out);
}

// round 6
// speedup vs baseline: 4.5296x; 1.1946x over previous
#include <cuda_runtime.h>
#include <math.h>

#define B 64
#define C 256
#define HW 64
#define L 21
#define SLOTS 42      // max needed rows: 2 per landmark
#define PITCH 66      // scalar col access conflict-free; float2 row access ok

// [f][l][b][c] window-average values, fp32, bit-matching reference f4
__device__ float g_f4[2 * L * B * C];
__device__ double g_kl[L];

// ---------------------------------------------------------------------------
// In-register inclusive scan over 64 elements, bit-identical to
// jax.lax.associative_scan (fp32). FADD(rn) commutative -> operand order
// matches the reference recursion bitwise.
// ---------------------------------------------------------------------------
__device__ __forceinline__ void scan64(float (&a)[64])
{
    #pragma unroll
    for (int d = 0; d < 6; ++d) {
        #pragma unroll
        for (int i = 0; i < (64 >> (d + 1)); ++i) {
            int hi = (i << (d + 1)) + (1 << (d + 1)) - 1;
            int lo = (i << (d + 1)) + (1 << d) - 1;
            a[hi] = __fadd_rn(a[lo], a[hi]);
        }
    }
    #pragma unroll
    for (int d = 4; d >= 0; --d) {
        #pragma unroll
        for (int i = 1; i < (64 >> (d + 1)); ++i) {
            int m = (i << (d + 1)) + (1 << d) - 1;
            a[m] = __fadd_rn(a[(i << (d + 1)) - 1], a[m]);
        }
    }
}

// ---------------------------------------------------------------------------
// Kernel A: integral-image corners via register-resident scans.
// Block = (f, b, channel pair). 128 threads: group g = tid>>6 owns channel
// cpair*2+g; t = tid&63 = column (phase 1) / row-slot (phase 2).
// Phase 1 loads columns DIRECTLY from global (coalesced across lanes),
// scans in registers, writes only needed rows to smem. Phase 2 scans only
// the needed rows.
// ---------------------------------------------------------------------------
__global__ __launch_bounds__(128) void pool_kernel(
    const float* __restrict__ f1, const float* __restrict__ f2,
    const float* __restrict__ pre1, const float* __restrict__ pre2)
{
    __shared__ float S1[2][SLOTS][PITCH];
    __shared__ int s_left[L], s_right[L], s_down[L], s_upper[L];
    __shared__ float s_s[L];
    __shared__ unsigned long long s_mask;
    __shared__ int s_nR;

    int bx = blockIdx.x;
    int cpair = bx & 127;          // C/2 = 128 channel pairs
    int fb = bx >> 7;
    int b = fb & 63;
    int f = fb >> 6;

    const float* feat = f ? f2 : f1;
    const float* pre  = f ? pre2 : pre1;

    int tid = threadIdx.x;
    int g = tid >> 6;
    int t = tid & 63;

    if (tid < L) {
        float x = pre[(b * L + tid) * 2 + 0];
        float y = pre[(b * L + tid) * 2 + 1];
        int left  = (int)fmaxf(x - 6.0f, 0.0f);   // clamp then trunc (non-neg)
        int right = (int)fminf(x + 6.0f, 63.0f);
        int down  = (int)fmaxf(y - 6.0f, 0.0f);
        int upper = (int)fminf(y + 6.0f, 63.0f);
        s_left[tid] = left;  s_right[tid] = right;
        s_down[tid] = down;  s_upper[tid] = upper;
        // divisor uses INCLUSIVE window (faithful quirk)
        s_s[tid] = (float)((upper - down + 1) * (right - left + 1));
    }
    __syncthreads();
    if (tid == 0) {
        unsigned long long m = 0;
        #pragma unroll
        for (int l = 0; l < L; ++l) {
            m |= 1ull << (s_right[l] - 1);         // right >= 6
            if (s_left[l] > 0) m |= 1ull << (s_left[l] - 1);
        }
        s_mask = m;
        s_nR = __popcll(m);
    }

    // ---- phase 1: column t loaded straight from global (coalesced) ----
    int c = cpair * 2 + g;
    const float* p = feat + ((size_t)b * C + c) * (HW * HW) + t;
    float a[64];
    #pragma unroll
    for (int j = 0; j < 64; ++j) a[j] = __ldg(p + j * HW);
    scan64(a);                                     // a[j] = P1[j][t]
    __syncthreads();                               // s_mask ready; S1 free
    unsigned long long mask = s_mask;
    int nR = s_nR;
    #pragma unroll
    for (int j = 0; j < 64; ++j) {
        if ((mask >> j) & 1ull) {
            int slot = __popcll(mask & ((1ull << j) - 1ull));
            S1[g][slot][t] = a[j];
        }
    }
    __syncthreads();

    // ---- phase 2: scan needed rows along w ----
    if (t < nR) {
        float r[64];
        #pragma unroll
        for (int k = 0; k < 32; ++k) {
            float2 v = *(const float2*)&S1[g][t][2 * k];
            r[2 * k] = v.x; r[2 * k + 1] = v.y;
        }
        scan64(r);                                 // r[w] = P2[row_t][w]
        #pragma unroll
        for (int k = 0; k < 32; ++k) {
            float2 v; v.x = r[2 * k]; v.y = r[2 * k + 1];
            *(float2*)&S1[g][t][2 * k] = v;        // in-place, thread-exclusive
        }
    }
    __syncthreads();

    // ---- corners: padded P[i][j] = (i>0 && j>0) ? P2[i-1][j-1] : 0 ----
    if (t < L) {
        int l = t;
        int left = s_left[l], right = s_right[l];
        int down = s_down[l], upper = s_upper[l];
        int sr = __popcll(mask & ((1ull << (right - 1)) - 1ull));
        float Pru = S1[g][sr][upper - 1];           // right,upper >= 6
        float Prd = (down > 0) ? S1[g][sr][down - 1] : 0.0f;
        float Plu = 0.0f, Pld = 0.0f;
        if (left > 0) {
            int sl = __popcll(mask & ((1ull << (left - 1)) - 1ull));
            Plu = S1[g][sl][upper - 1];
            if (down > 0) Pld = S1[g][sl][down - 1];
        }
        // jax eval order: ((Pru - Plu) - Prd) + Pld, fp32
        float rect = __fadd_rn(__fsub_rn(__fsub_rn(Pru, Plu), Prd), Pld);
        float f4 = rect / s_s[l];                   // IEEE fp32 div
        g_f4[(((size_t)f * L + l) * B + b) * C + c] = f4;
    }
}

// ---------------------------------------------------------------------------
// Kernel B: fp32 sequential batch mean + EMA (emulating XLA), fp64 downstream.
// One block per landmark, 256 threads = channels; contiguous g_f4 reads.
// ---------------------------------------------------------------------------
__global__ __launch_bounds__(256) void kl_kernel(
    const float* __restrict__ fea1, const float* __restrict__ fea2)
{
    int l = blockIdx.x;
    int c = threadIdx.x;

    float s1 = 0.0f, s2 = 0.0f;
    for (int bb = 0; bb < B; ++bb) {                 // sequential ascending
        s1 = __fadd_rn(s1, g_f4[(((size_t)0 * L + l) * B + bb) * C + c]);
        s2 = __fadd_rn(s2, g_f4[(((size_t)1 * L + l) * B + bb) * C + c]);
    }
    float m1 = __fdiv_rn(s1, 64.0f);                 // exact (pow2)
    float m2 = __fdiv_rn(s2, 64.0f);

    const float MM = 0.999f;
    const float OM = (float)(1.0 - 0.999);
    float fc1f = __fadd_rn(__fmul_rn(MM, m1), __fmul_rn(OM, fea1[l * C + c]));
    float fc2f = __fadd_rn(__fmul_rn(MM, m2), __fmul_rn(OM, fea2[l * C + c]));

    // ---- fp64 downstream (truth; ref's fp32 downstream error ~1e-4 rel) ----
    double fc1 = (double)fc1f, fc2 = (double)fc2f;

    __shared__ double sh[8];
    int warp = c >> 5, lane = c & 31;

    // block-max fc1
    double m = fc1;
    #pragma unroll
    for (int o = 16; o > 0; o >>= 1) {
        double tt = __shfl_xor_sync(0xffffffffu, m, o);
        m = fmax(m, tt);
    }
    if (lane == 0) sh[warp] = m;
    __syncthreads();
    m = sh[lane & 7];
    #pragma unroll
    for (int o = 4; o > 0; o >>= 1) {
        double tt = __shfl_xor_sync(0xffffffffu, m, o);
        m = fmax(m, tt);
    }

    // block-sum exp(fc1 - m)
    double se = exp(fc1 - m);
    #pragma unroll
    for (int o = 16; o > 0; o >>= 1) se += __shfl_xor_sync(0xffffffffu, se, o);
    __syncthreads();
    if (lane == 0) sh[warp] = se;
    __syncthreads();
    se = sh[lane & 7];
    #pragma unroll
    for (int o = 4; o > 0; o >>= 1) se += __shfl_xor_sync(0xffffffffu, se, o);

    double log_p = (fc1 - m) - log(se);

    // block-sum fc2
    double S2 = fc2;
    #pragma unroll
    for (int o = 16; o > 0; o >>= 1) S2 += __shfl_xor_sync(0xffffffffu, S2, o);
    __syncthreads();
    if (lane == 0) sh[warp] = S2;
    __syncthreads();
    S2 = sh[lane & 7];
    #pragma unroll
    for (int o = 4; o > 0; o >>= 1) S2 += __shfl_xor_sync(0xffffffffu, S2, o);

    double q = fc2 / S2;
    double term = (q > 0.0) ? q * (log(q) - log_p) : 0.0;

    // block-sum KL terms
    double kl = term;
    #pragma unroll
    for (int o = 16; o > 0; o >>= 1) kl += __shfl_xor_sync(0xffffffffu, kl, o);
    __syncthreads();
    if (lane == 0) sh[warp] = kl;
    __syncthreads();
    if (c == 0) {
        double tt = 0.0;
        #pragma unroll
        for (int w = 0; w < 8; ++w) tt += sh[w];
        g_kl[l] = tt;
    }
}

// ---------------------------------------------------------------------------
// Kernel C: mean over 21 landmarks -> fp32 scalar.
// ---------------------------------------------------------------------------
__global__ void final_kernel(float* __restrict__ out)
{
    int t = threadIdx.x;
    double v = (t < L) ? g_kl[t] : 0.0;
    #pragma unroll
    for (int o = 16; o > 0; o >>= 1) v += __shfl_xor_sync(0xffffffffu, v, o);
    if (t == 0) out[0] = (float)(v / 21.0);
}

extern "C" void kernel_launch(void* const* d_in, const int* in_sizes, int n_in,
                              void* d_out, int out_size)
{
    const float* f1   = (const float*)d_in[0];
    const float* f2   = (const float*)d_in[1];
    const float* pre1 = (const float*)d_in[2];
    const float* pre2 = (const float*)d_in[3];
    const float* fea1 = (const float*)d_in[4];
    const float* fea2 = (const float*)d_in[5];
    float* out = (float*)d_out;

    pool_kernel<<<2 * B * (C / 2), 128>>>(f1, f2, pre1, pre2);
    kl_kernel<<<L, 256>>>(fea1, fea2);
    final_kernel<<<1, 32>>>(out);
}

// round 11
// speedup vs baseline: 4.6282x; 1.0218x over previous
#include <cuda_runtime.h>
#include <math.h>

#define B 64
#define C 256
#define HW 64
#define L 21
#define SLOTS 42      // max needed rows: 2 per landmark
#define PITCH 66      // EVEN: float2 row accesses stay 8B-aligned (PITCH=65 trapped)

// [f][l][b][c] window-average values, fp32, bit-matching reference f4
__device__ float g_f4[2 * L * B * C];
__device__ double g_kl[L];

// ---------------------------------------------------------------------------
// Inclusive scan of 32 elements, bit-identical to jax.lax.associative_scan
// restricted to a 32-block (same pair tree; FADD(rn) commutative).
// ---------------------------------------------------------------------------
__device__ __forceinline__ void scan32(float (&a)[32])
{
    #pragma unroll
    for (int d = 0; d < 5; ++d) {
        #pragma unroll
        for (int i = 0; i < (32 >> (d + 1)); ++i) {
            int hi = (i << (d + 1)) + (1 << (d + 1)) - 1;
            int lo = (i << (d + 1)) + (1 << d) - 1;
            a[hi] = __fadd_rn(a[lo], a[hi]);
        }
    }
    #pragma unroll
    for (int d = 3; d >= 0; --d) {
        #pragma unroll
        for (int i = 1; i < (32 >> (d + 1)); ++i) {
            int m = (i << (d + 1)) + (1 << d) - 1;
            a[m] = __fadd_rn(a[(i << (d + 1)) - 1], a[m]);
        }
    }
}

// ---------------------------------------------------------------------------
// Upper half of the 64-scan given carry cl = inclusive total of lower half.
// Reproduces scan64's operations on positions 32..63 exactly:
//   up-sweep internal; u[31]=fadd(cl,u[31]) (the d=5 node); down-sweep where
//   the first mid of each level takes prefix cl, the rest internal.
// ---------------------------------------------------------------------------
__device__ __forceinline__ void scan32_carry(float (&u)[32], float cl)
{
    #pragma unroll
    for (int d = 0; d < 5; ++d) {
        #pragma unroll
        for (int i = 0; i < (32 >> (d + 1)); ++i) {
            int hi = (i << (d + 1)) + (1 << (d + 1)) - 1;
            int lo = (i << (d + 1)) + (1 << d) - 1;
            u[hi] = __fadd_rn(u[lo], u[hi]);
        }
    }
    u[31] = __fadd_rn(cl, u[31]);                 // scan64 d=5: a[63]=a[31]+a[63]
    #pragma unroll
    for (int d = 4; d >= 0; --d) {
        #pragma unroll
        for (int i = 0; i < (32 >> (d + 1)); ++i) {
            int m = (i << (d + 1)) + (1 << d) - 1;
            float pre = (i == 0) ? cl : u[(i << (d + 1)) - 1];
            u[m] = __fadd_rn(pre, u[m]);
        }
    }
}

// ---------------------------------------------------------------------------
// Kernel A: integral-image corners via register-resident scans.
// Block = (f, b, channel pair). 128 threads: group g = tid>>6 owns channel
// cpair*2+g; t = tid&63 = column (phase 1) / row-slot (phase 2).
// Column scan split into two 32-halves to stay spill-free.
// ---------------------------------------------------------------------------
__global__ __launch_bounds__(128) void pool_kernel(
    const float* __restrict__ f1, const float* __restrict__ f2,
    const float* __restrict__ pre1, const float* __restrict__ pre2)
{
    __shared__ __align__(16) float S1[2][SLOTS][PITCH];
    __shared__ int s_left[L], s_right[L], s_down[L], s_upper[L];
    __shared__ float s_s[L];
    __shared__ unsigned long long s_mask;
    __shared__ int s_nR;

    int bx = blockIdx.x;
    int cpair = bx & 127;          // C/2 = 128 channel pairs
    int fb = bx >> 7;
    int b = fb & 63;
    int f = fb >> 6;

    const float* feat = f ? f2 : f1;
    const float* pre  = f ? pre2 : pre1;

    int tid = threadIdx.x;
    int g = tid >> 6;
    int t = tid & 63;

    if (tid < L) {
        float x = pre[(b * L + tid) * 2 + 0];
        float y = pre[(b * L + tid) * 2 + 1];
        int left  = (int)fmaxf(x - 6.0f, 0.0f);   // clamp then trunc (non-neg)
        int right = (int)fminf(x + 6.0f, 63.0f);
        int down  = (int)fmaxf(y - 6.0f, 0.0f);
        int upper = (int)fminf(y + 6.0f, 63.0f);
        s_left[tid] = left;  s_right[tid] = right;
        s_down[tid] = down;  s_upper[tid] = upper;
        // divisor uses INCLUSIVE window (faithful quirk)
        s_s[tid] = (float)((upper - down + 1) * (right - left + 1));
    }
    __syncthreads();
    if (tid == 0) {
        unsigned long long m = 0;
        #pragma unroll
        for (int l = 0; l < L; ++l) {
            m |= 1ull << (s_right[l] - 1);         // right >= 6
            if (s_left[l] > 0) m |= 1ull << (s_left[l] - 1);
        }
        s_mask = m;
        s_nR = __popcll(m);
    }
    __syncthreads();
    unsigned long long mask = s_mask;
    int nR = s_nR;
    unsigned mlo = (unsigned)mask;
    unsigned mhi = (unsigned)(mask >> 32);

    // ---- phase 1: column t straight from global, two 32-halves ----
    int c = cpair * 2 + g;
    const float* p = feat + ((size_t)b * C + c) * (HW * HW) + t;

    float a[32];
    #pragma unroll
    for (int j = 0; j < 32; ++j) a[j] = __ldg(p + j * HW);
    scan32(a);                                     // a[j] = P1[j][t], j<32
    float cl = a[31];
    #pragma unroll
    for (int j = 0; j < 32; ++j) {
        if ((mlo >> j) & 1u) {
            int slot = __popc(mlo & ((1u << j) - 1u));
            S1[g][slot][t] = a[j];
        }
    }

    float u[32];
    #pragma unroll
    for (int j = 0; j < 32; ++j) u[j] = __ldg(p + (32 + j) * HW);
    scan32_carry(u, cl);                           // u[j] = P1[32+j][t]
    int base_hi = __popc(mlo);
    #pragma unroll
    for (int j = 0; j < 32; ++j) {
        if ((mhi >> j) & 1u) {
            int slot = base_hi + __popc(mhi & ((1u << j) - 1u));
            S1[g][slot][t] = u[j];
        }
    }
    __syncthreads();

    // ---- phase 2: scan needed rows along w (row fits one thread) ----
    if (t < nR) {
        float ra[32], ru[32];
        #pragma unroll
        for (int k = 0; k < 16; ++k) {
            float2 v = *(const float2*)&S1[g][t][2 * k];
            ra[2 * k] = v.x; ra[2 * k + 1] = v.y;
        }
        #pragma unroll
        for (int k = 0; k < 16; ++k) {
            float2 v = *(const float2*)&S1[g][t][32 + 2 * k];
            ru[2 * k] = v.x; ru[2 * k + 1] = v.y;
        }
        scan32(ra);
        scan32_carry(ru, ra[31]);
        #pragma unroll
        for (int k = 0; k < 16; ++k) {
            float2 v; v.x = ra[2 * k]; v.y = ra[2 * k + 1];
            *(float2*)&S1[g][t][2 * k] = v;        // in-place, thread-exclusive
        }
        #pragma unroll
        for (int k = 0; k < 16; ++k) {
            float2 v; v.x = ru[2 * k]; v.y = ru[2 * k + 1];
            *(float2*)&S1[g][t][32 + 2 * k] = v;
        }
    }
    __syncthreads();

    // ---- corners: padded P[i][j] = (i>0 && j>0) ? P2[i-1][j-1] : 0 ----
    if (t < L) {
        int l = t;
        int left = s_left[l], right = s_right[l];
        int down = s_down[l], upper = s_upper[l];
        int sr = __popcll(mask & ((1ull << (right - 1)) - 1ull));
        float Pru = S1[g][sr][upper - 1];           // right,upper >= 6
        float Prd = (down > 0) ? S1[g][sr][down - 1] : 0.0f;
        float Plu = 0.0f, Pld = 0.0f;
        if (left > 0) {
            int sl = __popcll(mask & ((1ull << (left - 1)) - 1ull));
            Plu = S1[g][sl][upper - 1];
            if (down > 0) Pld = S1[g][sl][down - 1];
        }
        // jax eval order: ((Pru - Plu) - Prd) + Pld, fp32
        float rect = __fadd_rn(__fsub_rn(__fsub_rn(Pru, Plu), Prd), Pld);
        float f4 = rect / s_s[l];                   // IEEE fp32 div
        g_f4[(((size_t)f * L + l) * B + b) * C + c] = f4;
    }
}

// ---------------------------------------------------------------------------
// Kernel B: fp32 sequential batch mean + EMA (emulating XLA), fp64 downstream.
// One block per landmark, 256 threads = channels; contiguous g_f4 reads.
// Loads fully unrolled (front-batched); add order unchanged (bit-exact).
// ---------------------------------------------------------------------------
__global__ __launch_bounds__(256) void kl_kernel(
    const float* __restrict__ fea1, const float* __restrict__ fea2)
{
    int l = blockIdx.x;
    int c = threadIdx.x;

    float v1[B], v2[B];
    #pragma unroll
    for (int bb = 0; bb < B; ++bb)
        v1[bb] = g_f4[(((size_t)0 * L + l) * B + bb) * C + c];
    #pragma unroll
    for (int bb = 0; bb < B; ++bb)
        v2[bb] = g_f4[(((size_t)1 * L + l) * B + bb) * C + c];

    float s1 = 0.0f, s2 = 0.0f;
    #pragma unroll
    for (int bb = 0; bb < B; ++bb) {                 // sequential ascending
        s1 = __fadd_rn(s1, v1[bb]);
        s2 = __fadd_rn(s2, v2[bb]);
    }
    float m1 = __fdiv_rn(s1, 64.0f);                 // exact (pow2)
    float m2 = __fdiv_rn(s2, 64.0f);

    const float MM = 0.999f;
    const float OM = (float)(1.0 - 0.999);
    float fc1f = __fadd_rn(__fmul_rn(MM, m1), __fmul_rn(OM, fea1[l * C + c]));
    float fc2f = __fadd_rn(__fmul_rn(MM, m2), __fmul_rn(OM, fea2[l * C + c]));

    // ---- fp64 downstream (truth; ref's fp32 downstream error ~1e-4 rel) ----
    double fc1 = (double)fc1f, fc2 = (double)fc2f;

    __shared__ double sh[8];
    int warp = c >> 5, lane = c & 31;

    // block-max fc1
    double m = fc1;
    #pragma unroll
    for (int o = 16; o > 0; o >>= 1) {
        double tt = __shfl_xor_sync(0xffffffffu, m, o);
        m = fmax(m, tt);
    }
    if (lane == 0) sh[warp] = m;
    __syncthreads();
    m = sh[lane & 7];
    #pragma unroll
    for (int o = 4; o > 0; o >>= 1) {
        double tt = __shfl_xor_sync(0xffffffffu, m, o);
        m = fmax(m, tt);
    }

    // block-sum exp(fc1 - m)
    double se = exp(fc1 - m);
    #pragma unroll
    for (int o = 16; o > 0; o >>= 1) se += __shfl_xor_sync(0xffffffffu, se, o);
    __syncthreads();
    if (lane == 0) sh[warp] = se;
    __syncthreads();
    se = sh[lane & 7];
    #pragma unroll
    for (int o = 4; o > 0; o >>= 1) se += __shfl_xor_sync(0xffffffffu, se, o);

    double log_p = (fc1 - m) - log(se);

    // block-sum fc2
    double S2 = fc2;
    #pragma unroll
    for (int o = 16; o > 0; o >>= 1) S2 += __shfl_xor_sync(0xffffffffu, S2, o);
    __syncthreads();
    if (lane == 0) sh[warp] = S2;
    __syncthreads();
    S2 = sh[lane & 7];
    #pragma unroll
    for (int o = 4; o > 0; o >>= 1) S2 += __shfl_xor_sync(0xffffffffu, S2, o);

    double q = fc2 / S2;
    double term = (q > 0.0) ? q * (log(q) - log_p) : 0.0;

    // block-sum KL terms
    double kl = term;
    #pragma unroll
    for (int o = 16; o > 0; o >>= 1) kl += __shfl_xor_sync(0xffffffffu, kl, o);
    __syncthreads();
    if (lane == 0) sh[warp] = kl;
    __syncthreads();
    if (c == 0) {
        double tt = 0.0;
        #pragma unroll
        for (int w = 0; w < 8; ++w) tt += sh[w];
        g_kl[l] = tt;
    }
}

// ---------------------------------------------------------------------------
// Kernel C: mean over 21 landmarks -> fp32 scalar.
// ---------------------------------------------------------------------------
__global__ void final_kernel(float* __restrict__ out)
{
    int t = threadIdx.x;
    double v = (t < L) ? g_kl[t] : 0.0;
    #pragma unroll
    for (int o = 16; o > 0; o >>= 1) v += __shfl_xor_sync(0xffffffffu, v, o);
    if (t == 0) out[0] = (float)(v / 21.0);
}

extern "C" void kernel_launch(void* const* d_in, const int* in_sizes, int n_in,
                              void* d_out, int out_size)
{
    const float* f1   = (const float*)d_in[0];
    const float* f2   = (const float*)d_in[1];
    const float* pre1 = (const float*)d_in[2];
    const float* pre2 = (const float*)d_in[3];
    const float* fea1 = (const float*)d_in[4];
    const float* fea2 = (const float*)d_in[5];
    float* out = (float*)d_out;

    pool_kernel<<<2 * B * (C / 2), 128>>>(f1, f2, pre1, pre2);
    kl_kernel<<<L, 256>>>(fea1, fea2);
    final_kernel<<<1, 32>>>(out);
}